// round 5
// baseline (speedup 1.0000x reference)
#include <cuda_runtime.h>
#include <cuda_bf16.h>
#include <cstdint>
#include <cstddef>

#define RTOT 32768
#define CINK 512
#define ETOT 640
#define ENT  320
#define DD   256

// ---------------- device scratch ----------------
__device__ __nv_bfloat16 g_p_hi[(size_t)RTOT * ETOT];
__device__ __nv_bfloat16 g_p_lo[(size_t)RTOT * ETOT];
__device__ float         g_Z[RTOT];
__device__ __nv_bfloat16 g_Whi[ETOT * CINK];
__device__ __nv_bfloat16 g_Wlo[ETOT * CINK];
__device__ __nv_bfloat16 g_CBThi[2 * DD * ENT];
__device__ __nv_bfloat16 g_CBTlo[2 * DD * ENT];

// ---------------- helpers ----------------
__device__ __forceinline__ uint32_t smem_u32(const void* p) {
    uint32_t a;
    asm("{ .reg .u64 t; cvta.to.shared.u64 t, %1; cvt.u32.u64 %0, t; }" : "=r"(a) : "l"(p));
    return a;
}
#define SWZ(o) ((uint32_t)(o) ^ ((((uint32_t)(o)) >> 3) & 0x70))

#define LDMX4(d, addr) \
    asm volatile("ldmatrix.sync.aligned.m8n8.x4.shared.b16 {%0,%1,%2,%3}, [%4];" \
                 : "=r"((d)[0]), "=r"((d)[1]), "=r"((d)[2]), "=r"((d)[3]) : "r"(addr))

#define MMA16(c, a, b0, b1) \
    asm volatile("mma.sync.aligned.m16n8k16.row.col.f32.bf16.bf16.f32 " \
                 "{%0,%1,%2,%3},{%4,%5,%6,%7},{%8,%9},{%0,%1,%2,%3};" \
                 : "+f"((c)[0]), "+f"((c)[1]), "+f"((c)[2]), "+f"((c)[3]) \
                 : "r"((a)[0]), "r"((a)[1]), "r"((a)[2]), "r"((a)[3]), "r"(b0), "r"(b1))

#define CP16(saddr, gptr) \
    asm volatile("cp.async.cg.shared.global [%0], [%1], 16;" :: "r"(saddr), "l"(gptr) : "memory")
#define CP_COMMIT() asm volatile("cp.async.commit_group;" ::: "memory")
#define CP_WAIT0()  asm volatile("cp.async.wait_group 0;" ::: "memory")

__device__ __forceinline__ void split1(float v, uint32_t& h, uint32_t& l) {
    __nv_bfloat16 hb = __float2bfloat16(v);
    h = __bfloat16_as_ushort(hb);
    l = __bfloat16_as_ushort(__float2bfloat16(v - __bfloat162float(hb)));
}

// Buffer layout inside 128KB dynamic smem: per buffer b (0/1):
//   AH = b*65536 + 0, AL = +16384, BH = +32768, BL = +49152   (each tile 128x64 bf16 = 16KB)
#define OFF_AH(b) ((b) * 65536 + 0)
#define OFF_AL(b) ((b) * 65536 + 16384)
#define OFF_BH(b) ((b) * 65536 + 32768)
#define OFF_BL(b) ((b) * 65536 + 49152)
static constexpr int SMEM_BYTES = 131072;

// 3-split MMA over one 128x128x64 chunk. acc += Ahi*Bhi + Ahi*Blo + Alo*Bhi.
__device__ __forceinline__ void compute_chunk(
    uint32_t saH, uint32_t saL, uint32_t sbH, uint32_t sbL,
    float acc[2][8][4], int lane, int wm, int wn)
{
    #pragma unroll
    for (int ks = 0; ks < 4; ks++) {
        uint32_t ah[2][4], al[2][4];
        #pragma unroll
        for (int mf = 0; mf < 2; mf++) {
            uint32_t so = SWZ((wm * 32 + mf * 16 + (lane & 15)) * 128 + ks * 32 + (lane >> 4) * 16);
            LDMX4(ah[mf], saH + so);
            LDMX4(al[mf], saL + so);
        }
        #pragma unroll
        for (int np = 0; np < 4; np++) {
            uint32_t so = SWZ((wn * 64 + np * 16 + ((lane >> 4) << 3) + (lane & 7)) * 128
                              + ks * 32 + ((lane >> 3) & 1) * 16);
            uint32_t bh[4], bl[4];
            LDMX4(bh, sbH + so);
            LDMX4(bl, sbL + so);
            #pragma unroll
            for (int mf = 0; mf < 2; mf++) {
                MMA16(acc[mf][2 * np],     ah[mf], bh[0], bh[1]);
                MMA16(acc[mf][2 * np + 1], ah[mf], bh[2], bh[3]);
                MMA16(acc[mf][2 * np],     ah[mf], bl[0], bl[1]);
                MMA16(acc[mf][2 * np + 1], ah[mf], bl[2], bl[3]);
                MMA16(acc[mf][2 * np],     al[mf], bh[0], bh[1]);
                MMA16(acc[mf][2 * np + 1], al[mf], bh[2], bh[3]);
            }
        }
    }
}

// ---------------- prep kernels ----------------
__global__ void split_w(const float* __restrict__ Wp) {
    int i = blockIdx.x * 256 + threadIdx.x;
    if (i < ETOT * CINK) {
        uint32_t h, l; split1(__ldg(Wp + i), h, l);
        g_Whi[i] = __ushort_as_bfloat16((unsigned short)h);
        g_Wlo[i] = __ushort_as_bfloat16((unsigned short)l);
    }
}
__global__ void split_cbt(const float* __restrict__ cb) {
    int i = blockIdx.x * 256 + threadIdx.x;   // i = (g*DD + d)*ENT + e
    if (i < 2 * DD * ENT) {
        int e = i % ENT, d = (i / ENT) % DD, g = i / (ENT * DD);
        uint32_t h, l; split1(__ldg(cb + ((size_t)g * ENT + e) * DD + d), h, l);
        g_CBThi[i] = __ushort_as_bfloat16((unsigned short)h);
        g_CBTlo[i] = __ushort_as_bfloat16((unsigned short)l);
    }
}

// ---------------- kernel 1: logits GEMM + fused exp(logit+bias+gumbel) ----------------
__global__ __launch_bounds__(256, 1) void gemm1(
    const float* __restrict__ x, const float* __restrict__ bp, const float* __restrict__ gum)
{
    extern __shared__ char smem[];
    const uint32_t sb = smem_u32(smem);
    const int tid = threadIdx.x, lane = tid & 31, wid = tid >> 5;
    const int wm = wid & 3, wn = wid >> 2;
    const int row0 = blockIdx.x * 128, bn0 = blockIdx.y * 128;

    float acc[2][8][4];
    #pragma unroll
    for (int i = 0; i < 2; i++)
        #pragma unroll
        for (int j = 0; j < 8; j++)
            #pragma unroll
            for (int q = 0; q < 4; q++) acc[i][j][q] = 0.f;

    // prologue: chunk 0
    {
        #pragma unroll
        for (int j = 0; j < 4; j++) {
            int i = tid + j * 256, r = i >> 3, c = i & 7;
            size_t go = (size_t)(bn0 + r) * CINK + c * 8;
            uint32_t so = SWZ(r * 128 + c * 16);
            CP16(sb + OFF_BH(0) + so, g_Whi + go);
            CP16(sb + OFF_BL(0) + so, g_Wlo + go);
        }
        CP_COMMIT();
        #pragma unroll
        for (int j = 0; j < 8; j++) {
            int i = tid + j * 256, r = i >> 4, c4 = i & 15;
            float4 v = __ldg((const float4*)(x + (size_t)(row0 + r) * CINK) + c4);
            uint32_t h0, l0, h1, l1, h2, l2, h3, l3;
            split1(v.x, h0, l0); split1(v.y, h1, l1); split1(v.z, h2, l2); split1(v.w, h3, l3);
            uint32_t so = SWZ(r * 128 + c4 * 8);
            *(uint2*)(smem + OFF_AH(0) + so) = make_uint2(h0 | (h1 << 16), h2 | (h3 << 16));
            *(uint2*)(smem + OFF_AL(0) + so) = make_uint2(l0 | (l1 << 16), l2 | (l3 << 16));
        }
        CP_WAIT0();
        __syncthreads();
    }

    int buf = 0;
    for (int kc = 0; kc < 8; kc++) {
        const int nb = buf ^ 1;
        float4 a_stage[8];
        if (kc < 7) {
            #pragma unroll
            for (int j = 0; j < 4; j++) {
                int i = tid + j * 256, r = i >> 3, c = i & 7;
                size_t go = (size_t)(bn0 + r) * CINK + (kc + 1) * 64 + c * 8;
                uint32_t so = SWZ(r * 128 + c * 16);
                CP16(sb + OFF_BH(nb) + so, g_Whi + go);
                CP16(sb + OFF_BL(nb) + so, g_Wlo + go);
            }
            CP_COMMIT();
            #pragma unroll
            for (int j = 0; j < 8; j++) {
                int i = tid + j * 256, r = i >> 4, c4 = i & 15;
                a_stage[j] = __ldg((const float4*)(x + (size_t)(row0 + r) * CINK + (kc + 1) * 64) + c4);
            }
        }
        compute_chunk(sb + OFF_AH(buf), sb + OFF_AL(buf), sb + OFF_BH(buf), sb + OFF_BL(buf),
                      acc, lane, wm, wn);
        if (kc < 7) {
            #pragma unroll
            for (int j = 0; j < 8; j++) {
                int i = tid + j * 256, r = i >> 4, c4 = i & 15;
                uint32_t h0, l0, h1, l1, h2, l2, h3, l3;
                split1(a_stage[j].x, h0, l0); split1(a_stage[j].y, h1, l1);
                split1(a_stage[j].z, h2, l2); split1(a_stage[j].w, h3, l3);
                uint32_t so = SWZ(r * 128 + c4 * 8);
                *(uint2*)(smem + OFF_AH(nb) + so) = make_uint2(h0 | (h1 << 16), h2 | (h3 << 16));
                *(uint2*)(smem + OFF_AL(nb) + so) = make_uint2(l0 | (l1 << 16), l2 | (l3 << 16));
            }
            CP_WAIT0();
        }
        __syncthreads();
        buf = nb;
    }

    // epilogue: p = exp(logit + bias + gumbel), store bf16 hi/lo
    #pragma unroll
    for (int mf = 0; mf < 2; mf++) {
        #pragma unroll
        for (int h = 0; h < 2; h++) {
            const int r = wm * 32 + mf * 16 + (lane >> 2) + h * 8;
            const size_t grow = row0 + r;
            #pragma unroll
            for (int nf = 0; nf < 8; nf++) {
                const int e = bn0 + wn * 64 + nf * 8 + (lane & 3) * 2;
                float2 gv = *(const float2*)(gum + grow * ETOT + e);
                float2 bv = *(const float2*)(bp + e);
                float p0 = __expf(acc[mf][nf][h * 2 + 0] + bv.x + gv.x);
                float p1 = __expf(acc[mf][nf][h * 2 + 1] + bv.y + gv.y);
                uint32_t h0, l0, h1, l1;
                split1(p0, h0, l0); split1(p1, h1, l1);
                *(uint32_t*)(g_p_hi + grow * ETOT + e) = h0 | (h1 << 16);
                *(uint32_t*)(g_p_lo + grow * ETOT + e) = l0 | (l1 << 16);
            }
        }
    }
}

// ---------------- Z kernel: deterministic per-row sum of p ----------------
__global__ __launch_bounds__(256) void zsum() {
    const int r = blockIdx.x * 8 + (threadIdx.x >> 5);
    const int lane = threadIdx.x & 31;
    const uint32_t* ph = (const uint32_t*)(g_p_hi + (size_t)r * ETOT);
    const uint32_t* pl = (const uint32_t*)(g_p_lo + (size_t)r * ETOT);
    float s = 0.f;
    #pragma unroll
    for (int i = lane; i < ETOT / 2; i += 32) {
        uint32_t hw = __ldg(ph + i), lw = __ldg(pl + i);
        float2 hf = __bfloat1622float2(*(const __nv_bfloat162*)&hw);
        float2 lf = __bfloat1622float2(*(const __nv_bfloat162*)&lw);
        s += (hf.x + lf.x) + (hf.y + lf.y);
    }
    #pragma unroll
    for (int o = 16; o; o >>= 1) s += __shfl_xor_sync(0xFFFFFFFFu, s, o);
    if (lane == 0) g_Z[r] = s;
}

// ---------------- kernel 2: block-diagonal codebook GEMM, /Z epilogue ----------------
__global__ __launch_bounds__(256, 1) void gemm2(float* __restrict__ out)
{
    extern __shared__ char smem[];
    const uint32_t sb = smem_u32(smem);
    const int tid = threadIdx.x, lane = tid & 31, wid = tid >> 5;
    const int wm = wid & 3, wn = wid >> 2;
    const int row0 = blockIdx.x * 128;
    const int g = blockIdx.y >> 1;            // group
    const int d0 = (blockIdx.y & 1) * 128;    // local d block
    const int oc0 = blockIdx.y * 128;         // output col base = g*256 + d0

    float acc[2][8][4];
    #pragma unroll
    for (int i = 0; i < 2; i++)
        #pragma unroll
        for (int j = 0; j < 8; j++)
            #pragma unroll
            for (int q = 0; q < 4; q++) acc[i][j][q] = 0.f;

    const size_t a_kbase = (size_t)g * ENT;

    // prologue chunk 0
    {
        #pragma unroll
        for (int j = 0; j < 4; j++) {
            int i = tid + j * 256, r = i >> 3, c = i & 7;
            uint32_t so = SWZ(r * 128 + c * 16);
            size_t ga = (size_t)(row0 + r) * ETOT + a_kbase + c * 8;
            size_t gb = (size_t)(g * DD + d0 + r) * ENT + c * 8;
            CP16(sb + OFF_AH(0) + so, g_p_hi + ga);
            CP16(sb + OFF_AL(0) + so, g_p_lo + ga);
            CP16(sb + OFF_BH(0) + so, g_CBThi + gb);
            CP16(sb + OFF_BL(0) + so, g_CBTlo + gb);
        }
        CP_COMMIT(); CP_WAIT0();
        __syncthreads();
    }

    int buf = 0;
    for (int kc = 0; kc < 5; kc++) {
        const int nb = buf ^ 1;
        if (kc < 4) {
            #pragma unroll
            for (int j = 0; j < 4; j++) {
                int i = tid + j * 256, r = i >> 3, c = i & 7;
                uint32_t so = SWZ(r * 128 + c * 16);
                size_t ga = (size_t)(row0 + r) * ETOT + a_kbase + (kc + 1) * 64 + c * 8;
                size_t gb = (size_t)(g * DD + d0 + r) * ENT + (kc + 1) * 64 + c * 8;
                CP16(sb + OFF_AH(nb) + so, g_p_hi + ga);
                CP16(sb + OFF_AL(nb) + so, g_p_lo + ga);
                CP16(sb + OFF_BH(nb) + so, g_CBThi + gb);
                CP16(sb + OFF_BL(nb) + so, g_CBTlo + gb);
            }
            CP_COMMIT();
        }
        compute_chunk(sb + OFF_AH(buf), sb + OFF_AL(buf), sb + OFF_BH(buf), sb + OFF_BL(buf),
                      acc, lane, wm, wn);
        if (kc < 4) CP_WAIT0();
        __syncthreads();
        buf = nb;
    }

    // epilogue: out = acc / Z
    #pragma unroll
    for (int mf = 0; mf < 2; mf++) {
        #pragma unroll
        for (int h = 0; h < 2; h++) {
            const int r = wm * 32 + mf * 16 + (lane >> 2) + h * 8;
            const size_t grow = row0 + r;
            const float rz = 1.0f / g_Z[grow];
            #pragma unroll
            for (int nf = 0; nf < 8; nf++) {
                const int oc = oc0 + wn * 64 + nf * 8 + (lane & 3) * 2;
                float2 o;
                o.x = acc[mf][nf][h * 2 + 0] * rz;
                o.y = acc[mf][nf][h * 2 + 1] * rz;
                *(float2*)(out + grow * 512 + oc) = o;
            }
        }
    }
}

// ---------------- launch ----------------
extern "C" void kernel_launch(void* const* d_in, const int* in_sizes, int n_in,
                              void* d_out, int out_size) {
    const float* x  = (const float*)d_in[0];
    const float* Wp = (const float*)d_in[1];
    const float* bp = (const float*)d_in[2];
    const float* cb = (const float*)d_in[3];
    const float* gu = (const float*)d_in[4];
    float* out = (float*)d_out;

    cudaFuncSetAttribute(gemm1, cudaFuncAttributeMaxDynamicSharedMemorySize, SMEM_BYTES);
    cudaFuncSetAttribute(gemm2, cudaFuncAttributeMaxDynamicSharedMemorySize, SMEM_BYTES);

    split_w<<<(ETOT * CINK + 255) / 256, 256>>>(Wp);
    split_cbt<<<(2 * DD * ENT + 255) / 256, 256>>>(cb);
    gemm1<<<dim3(RTOT / 128, ETOT / 128), 256, SMEM_BYTES>>>(x, bp, gu);
    zsum<<<RTOT / 8, 256>>>();
    gemm2<<<dim3(RTOT / 128, 4), 256, SMEM_BYTES>>>(out);
}

// round 7
// speedup vs baseline: 1.4978x; 1.4978x over previous
#include <cuda_runtime.h>
#include <cuda_bf16.h>
#include <cstdint>
#include <cstddef>

#define RTOT 32768
#define CINK 512
#define ETOT 640
#define ENT  320
#define DD   256

// ---------------- device scratch ----------------
__device__ __nv_bfloat16 g_xhi[(size_t)RTOT * CINK];
__device__ __nv_bfloat16 g_xlo[(size_t)RTOT * CINK];
__device__ __nv_bfloat16 g_p_hi[(size_t)RTOT * ETOT];
__device__ __nv_bfloat16 g_p_lo[(size_t)RTOT * ETOT];
__device__ float         g_Z[RTOT];
__device__ __nv_bfloat16 g_Whi[ETOT * CINK];
__device__ __nv_bfloat16 g_Wlo[ETOT * CINK];
__device__ __nv_bfloat16 g_CBThi[2 * DD * ENT];
__device__ __nv_bfloat16 g_CBTlo[2 * DD * ENT];

// ---------------- helpers ----------------
__device__ __forceinline__ uint32_t smem_u32(const void* p) {
    uint32_t a;
    asm("{ .reg .u64 t; cvta.to.shared.u64 t, %1; cvt.u32.u64 %0, t; }" : "=r"(a) : "l"(p));
    return a;
}
#define SWZ(o) ((uint32_t)(o) ^ ((((uint32_t)(o)) >> 3) & 0x70))

#define LDMX4(d, addr) \
    asm volatile("ldmatrix.sync.aligned.m8n8.x4.shared.b16 {%0,%1,%2,%3}, [%4];" \
                 : "=r"((d)[0]), "=r"((d)[1]), "=r"((d)[2]), "=r"((d)[3]) : "r"(addr))

#define MMA16(c, a, b0, b1) \
    asm volatile("mma.sync.aligned.m16n8k16.row.col.f32.bf16.bf16.f32 " \
                 "{%0,%1,%2,%3},{%4,%5,%6,%7},{%8,%9},{%0,%1,%2,%3};" \
                 : "+f"((c)[0]), "+f"((c)[1]), "+f"((c)[2]), "+f"((c)[3]) \
                 : "r"((a)[0]), "r"((a)[1]), "r"((a)[2]), "r"((a)[3]), "r"(b0), "r"(b1))

#define CP16(saddr, gptr) \
    asm volatile("cp.async.cg.shared.global [%0], [%1], 16;" :: "r"(saddr), "l"(gptr) : "memory")
#define CP_COMMIT() asm volatile("cp.async.commit_group;" ::: "memory")
#define CP_WAIT2()  asm volatile("cp.async.wait_group 2;" ::: "memory")

__device__ __forceinline__ void split1(float v, uint32_t& h, uint32_t& l) {
    __nv_bfloat16 hb = __float2bfloat16(v);
    h = __bfloat16_as_ushort(hb);
    l = __bfloat16_as_ushort(__float2bfloat16(v - __bfloat162float(hb)));
}

// 3 stages x 64KB: per stage: AH +0, AL +16384, BH +32768, BL +49152 (128x64 bf16 tiles)
#define STG 65536
static constexpr int SMEM_BYTES = 3 * STG;

// ---- 3-split MMA over one 128x128x64 chunk, 16 warps, warp tile 32x32 ----
__device__ __forceinline__ void compute_chunk(uint32_t base, float acc[2][4][4],
                                              int lane, int wm, int wn)
{
    const uint32_t saH = base, saL = base + 16384, sbH = base + 32768, sbL = base + 49152;
    #pragma unroll
    for (int ks = 0; ks < 4; ks++) {
        uint32_t ah[2][4], al[2][4];
        #pragma unroll
        for (int mf = 0; mf < 2; mf++) {
            uint32_t so = SWZ((wm * 32 + mf * 16 + (lane & 15)) * 128 + ks * 32 + (lane >> 4) * 16);
            LDMX4(ah[mf], saH + so);
            LDMX4(al[mf], saL + so);
        }
        #pragma unroll
        for (int np = 0; np < 2; np++) {
            uint32_t so = SWZ((wn * 32 + np * 16 + ((lane >> 4) << 3) + (lane & 7)) * 128
                              + ks * 32 + ((lane >> 3) & 1) * 16);
            uint32_t bh[4], bl[4];
            LDMX4(bh, sbH + so);
            LDMX4(bl, sbL + so);
            #pragma unroll
            for (int mf = 0; mf < 2; mf++) {
                MMA16(acc[mf][2 * np],     ah[mf], bh[0], bh[1]);
                MMA16(acc[mf][2 * np + 1], ah[mf], bh[2], bh[3]);
                MMA16(acc[mf][2 * np],     ah[mf], bl[0], bl[1]);
                MMA16(acc[mf][2 * np + 1], ah[mf], bl[2], bl[3]);
                MMA16(acc[mf][2 * np],     al[mf], bh[0], bh[1]);
                MMA16(acc[mf][2 * np + 1], al[mf], bh[2], bh[3]);
            }
        }
    }
}

// ---------------- prep kernels ----------------
__global__ void split_x(const float* __restrict__ x) {
    size_t i = (size_t)blockIdx.x * 256 + threadIdx.x;   // one float4 per thread
    float4 v = __ldg((const float4*)x + i);
    uint32_t h0, l0, h1, l1, h2, l2, h3, l3;
    split1(v.x, h0, l0); split1(v.y, h1, l1); split1(v.z, h2, l2); split1(v.w, h3, l3);
    *(uint2*)(g_xhi + i * 4) = make_uint2(h0 | (h1 << 16), h2 | (h3 << 16));
    *(uint2*)(g_xlo + i * 4) = make_uint2(l0 | (l1 << 16), l2 | (l3 << 16));
}
__global__ void split_w(const float* __restrict__ Wp) {
    int i = blockIdx.x * 256 + threadIdx.x;
    if (i < ETOT * CINK) {
        uint32_t h, l; split1(__ldg(Wp + i), h, l);
        g_Whi[i] = __ushort_as_bfloat16((unsigned short)h);
        g_Wlo[i] = __ushort_as_bfloat16((unsigned short)l);
    }
}
__global__ void split_cbt(const float* __restrict__ cb) {
    int i = blockIdx.x * 256 + threadIdx.x;   // i = (g*DD + d)*ENT + e
    if (i < 2 * DD * ENT) {
        int e = i % ENT, d = (i / ENT) % DD, g = i / (ENT * DD);
        uint32_t h, l; split1(__ldg(cb + ((size_t)g * ENT + e) * DD + d), h, l);
        g_CBThi[i] = __ushort_as_bfloat16((unsigned short)h);
        g_CBTlo[i] = __ushort_as_bfloat16((unsigned short)l);
    }
}

// ---------------- kernel 1: logits GEMM + fused exp(logit+bias+gumbel) ----------------
__device__ __forceinline__ void g1_load(uint32_t sb, int tid, int row0, int bn0, int kc, int slot) {
    const uint32_t base = sb + slot * STG;
    #pragma unroll
    for (int j = 0; j < 2; j++) {
        int i = tid + j * 512, r = i >> 3, c = i & 7;
        uint32_t so = SWZ(r * 128 + c * 16);
        size_t ga = (size_t)(row0 + r) * CINK + kc * 64 + c * 8;
        size_t gb = (size_t)(bn0 + r) * CINK + kc * 64 + c * 8;
        CP16(base + so,         g_xhi + ga);
        CP16(base + 16384 + so, g_xlo + ga);
        CP16(base + 32768 + so, g_Whi + gb);
        CP16(base + 49152 + so, g_Wlo + gb);
    }
}

__global__ __launch_bounds__(512, 1) void gemm1(
    const float* __restrict__ bp, const float* __restrict__ gum)
{
    extern __shared__ char smem[];
    const uint32_t sb = smem_u32(smem);
    const int tid = threadIdx.x, lane = tid & 31, wid = tid >> 5;
    const int wm = wid & 3, wn = wid >> 2;
    const int row0 = blockIdx.x * 128, bn0 = blockIdx.y * 128;

    float acc[2][4][4];
    #pragma unroll
    for (int i = 0; i < 2; i++)
        #pragma unroll
        for (int j = 0; j < 4; j++)
            #pragma unroll
            for (int q = 0; q < 4; q++) acc[i][j][q] = 0.f;

    g1_load(sb, tid, row0, bn0, 0, 0); CP_COMMIT();
    g1_load(sb, tid, row0, bn0, 1, 1); CP_COMMIT();

    for (int kc = 0; kc < 8; kc++) {
        if (kc + 2 < 8) g1_load(sb, tid, row0, bn0, kc + 2, (kc + 2) % 3);
        CP_COMMIT();                 // empty groups keep the count uniform
        CP_WAIT2();                  // group kc complete
        __syncthreads();
        compute_chunk(sb + (kc % 3) * STG, acc, lane, wm, wn);
        __syncthreads();
    }

    // epilogue: p = exp(logit + bias + gumbel), store bf16 hi/lo
    #pragma unroll
    for (int mf = 0; mf < 2; mf++) {
        #pragma unroll
        for (int h = 0; h < 2; h++) {
            const int r = wm * 32 + mf * 16 + (lane >> 2) + h * 8;
            const size_t grow = row0 + r;
            #pragma unroll
            for (int nf = 0; nf < 4; nf++) {
                const int e = bn0 + wn * 32 + nf * 8 + (lane & 3) * 2;
                float2 gv = *(const float2*)(gum + grow * ETOT + e);
                float2 bv = *(const float2*)(bp + e);
                float p0 = __expf(acc[mf][nf][h * 2 + 0] + bv.x + gv.x);
                float p1 = __expf(acc[mf][nf][h * 2 + 1] + bv.y + gv.y);
                uint32_t h0, l0, h1, l1;
                split1(p0, h0, l0); split1(p1, h1, l1);
                *(uint32_t*)(g_p_hi + grow * ETOT + e) = h0 | (h1 << 16);
                *(uint32_t*)(g_p_lo + grow * ETOT + e) = l0 | (l1 << 16);
            }
        }
    }
}

// ---------------- Z kernel: deterministic per-row sum of p ----------------
__global__ __launch_bounds__(256) void zsum() {
    const int r = blockIdx.x * 8 + (threadIdx.x >> 5);
    const int lane = threadIdx.x & 31;
    const uint32_t* ph = (const uint32_t*)(g_p_hi + (size_t)r * ETOT);
    const uint32_t* pl = (const uint32_t*)(g_p_lo + (size_t)r * ETOT);
    float s = 0.f;
    #pragma unroll
    for (int i = lane; i < ETOT / 2; i += 32) {
        uint32_t hw = __ldg(ph + i), lw = __ldg(pl + i);
        float2 hf = __bfloat1622float2(*(const __nv_bfloat162*)&hw);
        float2 lf = __bfloat1622float2(*(const __nv_bfloat162*)&lw);
        s += (hf.x + lf.x) + (hf.y + lf.y);
    }
    #pragma unroll
    for (int o = 16; o; o >>= 1) s += __shfl_xor_sync(0xFFFFFFFFu, s, o);
    if (lane == 0) g_Z[r] = s;
}

// ---------------- kernel 2: block-diagonal codebook GEMM, /Z epilogue ----------------
__device__ __forceinline__ void g2_load(uint32_t sb, int tid, int row0, int g, int d0,
                                        int kc, int slot) {
    const uint32_t base = sb + slot * STG;
    #pragma unroll
    for (int j = 0; j < 2; j++) {
        int i = tid + j * 512, r = i >> 3, c = i & 7;
        uint32_t so = SWZ(r * 128 + c * 16);
        size_t ga = (size_t)(row0 + r) * ETOT + (size_t)g * ENT + kc * 64 + c * 8;
        size_t gb = (size_t)(g * DD + d0 + r) * ENT + kc * 64 + c * 8;
        CP16(base + so,         g_p_hi + ga);
        CP16(base + 16384 + so, g_p_lo + ga);
        CP16(base + 32768 + so, g_CBThi + gb);
        CP16(base + 49152 + so, g_CBTlo + gb);
    }
}

__global__ __launch_bounds__(512, 1) void gemm2(float* __restrict__ out)
{
    extern __shared__ char smem[];
    const uint32_t sb = smem_u32(smem);
    const int tid = threadIdx.x, lane = tid & 31, wid = tid >> 5;
    const int wm = wid & 3, wn = wid >> 2;
    const int row0 = blockIdx.x * 128;
    const int g = blockIdx.y >> 1;
    const int d0 = (blockIdx.y & 1) * 128;
    const int oc0 = blockIdx.y * 128;

    float acc[2][4][4];
    #pragma unroll
    for (int i = 0; i < 2; i++)
        #pragma unroll
        for (int j = 0; j < 4; j++)
            #pragma unroll
            for (int q = 0; q < 4; q++) acc[i][j][q] = 0.f;

    g2_load(sb, tid, row0, g, d0, 0, 0); CP_COMMIT();
    g2_load(sb, tid, row0, g, d0, 1, 1); CP_COMMIT();

    for (int kc = 0; kc < 5; kc++) {
        if (kc + 2 < 5) g2_load(sb, tid, row0, g, d0, kc + 2, (kc + 2) % 3);
        CP_COMMIT();
        CP_WAIT2();
        __syncthreads();
        compute_chunk(sb + (kc % 3) * STG, acc, lane, wm, wn);
        __syncthreads();
    }

    // epilogue: out = acc / Z
    #pragma unroll
    for (int mf = 0; mf < 2; mf++) {
        #pragma unroll
        for (int h = 0; h < 2; h++) {
            const int r = wm * 32 + mf * 16 + (lane >> 2) + h * 8;
            const size_t grow = row0 + r;
            const float rz = 1.0f / g_Z[grow];
            #pragma unroll
            for (int nf = 0; nf < 4; nf++) {
                const int oc = oc0 + wn * 32 + nf * 8 + (lane & 3) * 2;
                float2 o;
                o.x = acc[mf][nf][h * 2 + 0] * rz;
                o.y = acc[mf][nf][h * 2 + 1] * rz;
                *(float2*)(out + grow * 512 + oc) = o;
            }
        }
    }
}

// ---------------- launch ----------------
extern "C" void kernel_launch(void* const* d_in, const int* in_sizes, int n_in,
                              void* d_out, int out_size) {
    const float* x  = (const float*)d_in[0];
    const float* Wp = (const float*)d_in[1];
    const float* bp = (const float*)d_in[2];
    const float* cb = (const float*)d_in[3];
    const float* gu = (const float*)d_in[4];
    float* out = (float*)d_out;

    cudaFuncSetAttribute(gemm1, cudaFuncAttributeMaxDynamicSharedMemorySize, SMEM_BYTES);
    cudaFuncSetAttribute(gemm2, cudaFuncAttributeMaxDynamicSharedMemorySize, SMEM_BYTES);

    split_x<<<(RTOT * CINK / 4) / 256, 256>>>(x);
    split_w<<<(ETOT * CINK + 255) / 256, 256>>>(Wp);
    split_cbt<<<(2 * DD * ENT + 255) / 256, 256>>>(cb);
    gemm1<<<dim3(RTOT / 128, ETOT / 128), 512, SMEM_BYTES>>>(bp, gu);
    zsum<<<RTOT / 8, 256>>>();
    gemm2<<<dim3(RTOT / 128, 4), 512, SMEM_BYTES>>>(out);
}

// round 8
// speedup vs baseline: 1.5881x; 1.0603x over previous
#include <cuda_runtime.h>
#include <cuda_bf16.h>
#include <cstdint>
#include <cstddef>

#define RTOT 32768
#define CINK 512
#define ETOT 640
#define ENT  320
#define DD   256

// ---------------- device scratch ----------------
__device__ __nv_bfloat16 g_xhi[(size_t)RTOT * CINK];
__device__ __nv_bfloat16 g_xlo[(size_t)RTOT * CINK];
__device__ __nv_bfloat16 g_p_hi[(size_t)RTOT * ETOT];
__device__ __nv_bfloat16 g_p_lo[(size_t)RTOT * ETOT];
__device__ float         g_Z[RTOT];
__device__ __nv_bfloat16 g_Whi[ETOT * CINK];
__device__ __nv_bfloat16 g_Wlo[ETOT * CINK];
__device__ __nv_bfloat16 g_CBThi[2 * DD * ENT];
__device__ __nv_bfloat16 g_CBTlo[2 * DD * ENT];

// ---------------- helpers ----------------
__device__ __forceinline__ uint32_t smem_u32(const void* p) {
    uint32_t a;
    asm("{ .reg .u64 t; cvta.to.shared.u64 t, %1; cvt.u32.u64 %0, t; }" : "=r"(a) : "l"(p));
    return a;
}
#define SWZ(o) ((uint32_t)(o) ^ ((((uint32_t)(o)) >> 3) & 0x70))

#define LDMX4(d, addr) \
    asm volatile("ldmatrix.sync.aligned.m8n8.x4.shared.b16 {%0,%1,%2,%3}, [%4];" \
                 : "=r"((d)[0]), "=r"((d)[1]), "=r"((d)[2]), "=r"((d)[3]) : "r"(addr))

#define MMA16(c, a, b0, b1) \
    asm volatile("mma.sync.aligned.m16n8k16.row.col.f32.bf16.bf16.f32 " \
                 "{%0,%1,%2,%3},{%4,%5,%6,%7},{%8,%9},{%0,%1,%2,%3};" \
                 : "+f"((c)[0]), "+f"((c)[1]), "+f"((c)[2]), "+f"((c)[3]) \
                 : "r"((a)[0]), "r"((a)[1]), "r"((a)[2]), "r"((a)[3]), "r"(b0), "r"(b1))

#define CP16(saddr, gptr) \
    asm volatile("cp.async.cg.shared.global [%0], [%1], 16;" :: "r"(saddr), "l"(gptr) : "memory")
#define CP_COMMIT() asm volatile("cp.async.commit_group;" ::: "memory")
#define CP_WAIT2()  asm volatile("cp.async.wait_group 2;" ::: "memory")

__device__ __forceinline__ void split1(float v, uint32_t& h, uint32_t& l) {
    __nv_bfloat16 hb = __float2bfloat16(v);
    h = __bfloat16_as_ushort(hb);
    l = __bfloat16_as_ushort(__float2bfloat16(v - __bfloat162float(hb)));
}

// Stage = 32KB: A tile [128r x (32 hi | 32 lo) cols] = 16KB at +0, B tile same at +16384.
// Rows are 128B (hi cols 0..31 in bytes [0,64), lo in [64,128)) -> SW128 swizzle valid.
#define STG 32768
static constexpr int SMEM_BYTES = 3 * STG;   // 96KB/CTA -> 2 CTAs/SM

// ---- 3-split MMA over one 128x128x32 chunk; 8 warps, warp tile 32x64 ----
__device__ __forceinline__ void compute_chunk(uint32_t base, float acc[2][8][4],
                                              int lane, int wm, int wn)
{
    const uint32_t saA = base, saB = base + 16384;
    #pragma unroll
    for (int ks = 0; ks < 2; ks++) {
        uint32_t ah[2][4], al[2][4];
        const uint32_t kb = ks * 32 + (lane >> 4) * 16;
        #pragma unroll
        for (int mf = 0; mf < 2; mf++) {
            uint32_t rb = (wm * 32 + mf * 16 + (lane & 15)) * 128;
            LDMX4(ah[mf], saA + SWZ(rb + kb));
            LDMX4(al[mf], saA + SWZ(rb + 64 + kb));
        }
        const uint32_t kbB = ks * 32 + ((lane >> 3) & 1) * 16;
        #pragma unroll
        for (int np = 0; np < 4; np++) {
            uint32_t rb = (wn * 64 + np * 16 + ((lane >> 4) << 3) + (lane & 7)) * 128;
            uint32_t bh[4], bl[4];
            LDMX4(bh, saB + SWZ(rb + kbB));
            LDMX4(bl, saB + SWZ(rb + 64 + kbB));
            #pragma unroll
            for (int mf = 0; mf < 2; mf++) {
                MMA16(acc[mf][2 * np],     ah[mf], bh[0], bh[1]);
                MMA16(acc[mf][2 * np + 1], ah[mf], bh[2], bh[3]);
                MMA16(acc[mf][2 * np],     ah[mf], bl[0], bl[1]);
                MMA16(acc[mf][2 * np + 1], ah[mf], bl[2], bl[3]);
                MMA16(acc[mf][2 * np],     al[mf], bh[0], bh[1]);
                MMA16(acc[mf][2 * np + 1], al[mf], bh[2], bh[3]);
            }
        }
    }
}

// Generic stage loader: A rows from (ahi/alo + aoff + r*astr), B rows from (bhi/blo + boff + r*bstr),
// 32 K-cols starting at k0. Each of 256 threads: 4 iterations x 2 cp.async.
__device__ __forceinline__ void load_stage(uint32_t base, int tid,
    const __nv_bfloat16* __restrict__ ahi, const __nv_bfloat16* __restrict__ alo,
    size_t aoff, int astr,
    const __nv_bfloat16* __restrict__ bhi, const __nv_bfloat16* __restrict__ blo,
    size_t boff, int bstr, int k0)
{
    #pragma unroll
    for (int j = 0; j < 4; j++) {
        int i = tid + j * 256;           // 0..1023
        int r = i >> 3, c = i & 7;       // r 0..127, c 0..7
        int hi = (c < 4), cc = c & 3;
        uint32_t dst = SWZ(r * 128 + (hi ? 0 : 64) + cc * 16);
        const __nv_bfloat16* asrc = (hi ? ahi : alo) + aoff + (size_t)r * astr + k0 + cc * 8;
        const __nv_bfloat16* bsrc = (hi ? bhi : blo) + boff + (size_t)r * bstr + k0 + cc * 8;
        CP16(base + dst,         asrc);
        CP16(base + 16384 + dst, bsrc);
    }
}

// ---------------- prep kernels ----------------
__global__ void split_x(const float* __restrict__ x) {
    size_t i = (size_t)blockIdx.x * 256 + threadIdx.x;
    float4 v = __ldg((const float4*)x + i);
    uint32_t h0, l0, h1, l1, h2, l2, h3, l3;
    split1(v.x, h0, l0); split1(v.y, h1, l1); split1(v.z, h2, l2); split1(v.w, h3, l3);
    *(uint2*)(g_xhi + i * 4) = make_uint2(h0 | (h1 << 16), h2 | (h3 << 16));
    *(uint2*)(g_xlo + i * 4) = make_uint2(l0 | (l1 << 16), l2 | (l3 << 16));
}
__global__ void split_w(const float* __restrict__ Wp) {
    int i = blockIdx.x * 256 + threadIdx.x;
    if (i < ETOT * CINK) {
        uint32_t h, l; split1(__ldg(Wp + i), h, l);
        g_Whi[i] = __ushort_as_bfloat16((unsigned short)h);
        g_Wlo[i] = __ushort_as_bfloat16((unsigned short)l);
    }
}
__global__ void split_cbt(const float* __restrict__ cb) {
    int i = blockIdx.x * 256 + threadIdx.x;   // i = (g*DD + d)*ENT + e
    if (i < 2 * DD * ENT) {
        int e = i % ENT, d = (i / ENT) % DD, g = i / (ENT * DD);
        uint32_t h, l; split1(__ldg(cb + ((size_t)g * ENT + e) * DD + d), h, l);
        g_CBThi[i] = __ushort_as_bfloat16((unsigned short)h);
        g_CBTlo[i] = __ushort_as_bfloat16((unsigned short)l);
    }
}

// ---------------- kernel 1: logits GEMM + fused exp(logit+bias+gumbel) ----------------
__global__ __launch_bounds__(256, 2) void gemm1(
    const float* __restrict__ bp, const float* __restrict__ gum)
{
    extern __shared__ char smem[];
    const uint32_t sb = smem_u32(smem);
    const int tid = threadIdx.x, lane = tid & 31, wid = tid >> 5;
    const int wm = wid & 3, wn = wid >> 2;           // 4 M-warps x 2 N-warps
    const int row0 = blockIdx.x * 128, bn0 = blockIdx.y * 128;

    float acc[2][8][4];
    #pragma unroll
    for (int i = 0; i < 2; i++)
        #pragma unroll
        for (int j = 0; j < 8; j++)
            #pragma unroll
            for (int q = 0; q < 4; q++) acc[i][j][q] = 0.f;

    load_stage(sb,       tid, g_xhi, g_xlo, (size_t)row0 * CINK, CINK,
               g_Whi, g_Wlo, (size_t)bn0 * CINK, CINK, 0);  CP_COMMIT();
    load_stage(sb + STG, tid, g_xhi, g_xlo, (size_t)row0 * CINK, CINK,
               g_Whi, g_Wlo, (size_t)bn0 * CINK, CINK, 32); CP_COMMIT();

    for (int kc = 0; kc < 16; kc++) {                 // K chunks of 32
        if (kc + 2 < 16)
            load_stage(sb + ((kc + 2) % 3) * STG, tid, g_xhi, g_xlo, (size_t)row0 * CINK, CINK,
                       g_Whi, g_Wlo, (size_t)bn0 * CINK, CINK, (kc + 2) * 32);
        CP_COMMIT();                  // empty groups keep the count uniform
        CP_WAIT2();
        __syncthreads();
        compute_chunk(sb + (kc % 3) * STG, acc, lane, wm, wn);
        __syncthreads();
    }

    // epilogue: p = exp(logit + bias + gumbel), store bf16 hi/lo
    #pragma unroll
    for (int mf = 0; mf < 2; mf++) {
        #pragma unroll
        for (int h = 0; h < 2; h++) {
            const int r = wm * 32 + mf * 16 + (lane >> 2) + h * 8;
            const size_t grow = row0 + r;
            #pragma unroll
            for (int nf = 0; nf < 8; nf++) {
                const int e = bn0 + wn * 64 + nf * 8 + (lane & 3) * 2;
                float2 gv = *(const float2*)(gum + grow * ETOT + e);
                float2 bv = *(const float2*)(bp + e);
                float p0 = __expf(acc[mf][nf][h * 2 + 0] + bv.x + gv.x);
                float p1 = __expf(acc[mf][nf][h * 2 + 1] + bv.y + gv.y);
                uint32_t h0, l0, h1, l1;
                split1(p0, h0, l0); split1(p1, h1, l1);
                *(uint32_t*)(g_p_hi + grow * ETOT + e) = h0 | (h1 << 16);
                *(uint32_t*)(g_p_lo + grow * ETOT + e) = l0 | (l1 << 16);
            }
        }
    }
}

// ---------------- Z kernel: deterministic per-row sum of p ----------------
__global__ __launch_bounds__(256) void zsum() {
    const int r = blockIdx.x * 8 + (threadIdx.x >> 5);
    const int lane = threadIdx.x & 31;
    const uint32_t* ph = (const uint32_t*)(g_p_hi + (size_t)r * ETOT);
    const uint32_t* pl = (const uint32_t*)(g_p_lo + (size_t)r * ETOT);
    float s = 0.f;
    #pragma unroll
    for (int i = lane; i < ETOT / 2; i += 32) {
        uint32_t hw = __ldg(ph + i), lw = __ldg(pl + i);
        float2 hf = __bfloat1622float2(*(const __nv_bfloat162*)&hw);
        float2 lf = __bfloat1622float2(*(const __nv_bfloat162*)&lw);
        s += (hf.x + lf.x) + (hf.y + lf.y);
    }
    #pragma unroll
    for (int o = 16; o; o >>= 1) s += __shfl_xor_sync(0xFFFFFFFFu, s, o);
    if (lane == 0) g_Z[r] = s;
}

// ---------------- kernel 2: block-diagonal codebook GEMM, /Z epilogue ----------------
__global__ __launch_bounds__(256, 2) void gemm2(float* __restrict__ out)
{
    extern __shared__ char smem[];
    const uint32_t sb = smem_u32(smem);
    const int tid = threadIdx.x, lane = tid & 31, wid = tid >> 5;
    const int wm = wid & 3, wn = wid >> 2;
    const int row0 = blockIdx.x * 128;
    const int g = blockIdx.y >> 1;
    const int d0 = (blockIdx.y & 1) * 128;
    const int oc0 = blockIdx.y * 128;

    float acc[2][8][4];
    #pragma unroll
    for (int i = 0; i < 2; i++)
        #pragma unroll
        for (int j = 0; j < 8; j++)
            #pragma unroll
            for (int q = 0; q < 4; q++) acc[i][j][q] = 0.f;

    const size_t aoff = (size_t)row0 * ETOT + (size_t)g * ENT;
    const size_t boff = (size_t)(g * DD + d0) * ENT;

    load_stage(sb,       tid, g_p_hi, g_p_lo, aoff, ETOT, g_CBThi, g_CBTlo, boff, ENT, 0);  CP_COMMIT();
    load_stage(sb + STG, tid, g_p_hi, g_p_lo, aoff, ETOT, g_CBThi, g_CBTlo, boff, ENT, 32); CP_COMMIT();

    for (int kc = 0; kc < 10; kc++) {                 // 320 / 32
        if (kc + 2 < 10)
            load_stage(sb + ((kc + 2) % 3) * STG, tid, g_p_hi, g_p_lo, aoff, ETOT,
                       g_CBThi, g_CBTlo, boff, ENT, (kc + 2) * 32);
        CP_COMMIT();
        CP_WAIT2();
        __syncthreads();
        compute_chunk(sb + (kc % 3) * STG, acc, lane, wm, wn);
        __syncthreads();
    }

    // epilogue: out = acc / Z
    #pragma unroll
    for (int mf = 0; mf < 2; mf++) {
        #pragma unroll
        for (int h = 0; h < 2; h++) {
            const int r = wm * 32 + mf * 16 + (lane >> 2) + h * 8;
            const size_t grow = row0 + r;
            const float rz = 1.0f / g_Z[grow];
            #pragma unroll
            for (int nf = 0; nf < 8; nf++) {
                const int oc = oc0 + wn * 64 + nf * 8 + (lane & 3) * 2;
                float2 o;
                o.x = acc[mf][nf][h * 2 + 0] * rz;
                o.y = acc[mf][nf][h * 2 + 1] * rz;
                *(float2*)(out + grow * 512 + oc) = o;
            }
        }
    }
}

// ---------------- launch ----------------
extern "C" void kernel_launch(void* const* d_in, const int* in_sizes, int n_in,
                              void* d_out, int out_size) {
    const float* x  = (const float*)d_in[0];
    const float* Wp = (const float*)d_in[1];
    const float* bp = (const float*)d_in[2];
    const float* cb = (const float*)d_in[3];
    const float* gu = (const float*)d_in[4];
    float* out = (float*)d_out;

    cudaFuncSetAttribute(gemm1, cudaFuncAttributeMaxDynamicSharedMemorySize, SMEM_BYTES);
    cudaFuncSetAttribute(gemm2, cudaFuncAttributeMaxDynamicSharedMemorySize, SMEM_BYTES);

    split_x<<<(RTOT * CINK / 4) / 256, 256>>>(x);
    split_w<<<(ETOT * CINK + 255) / 256, 256>>>(Wp);
    split_cbt<<<(2 * DD * ENT + 255) / 256, 256>>>(cb);
    gemm1<<<dim3(RTOT / 128, ETOT / 128), 256, SMEM_BYTES>>>(bp, gu);
    zsum<<<RTOT / 8, 256>>>();
    gemm2<<<dim3(RTOT / 128, 4), 256, SMEM_BYTES>>>(out);
}